// round 6
// baseline (speedup 1.0000x reference)
#include <cuda_runtime.h>
#include <cuda_fp16.h>
#include <mma.h>
#include <math.h>

using namespace nvcuda;

#define VOCAB 5000
#define EMB   512
#define HID   1024
#define GATES 4096
#define BATCH 32
#define SEQ   512
#define MROWS (BATCH*SEQ)   /* 16384 */
#define VPAD  5120          /* 40 * 128 */

#define JPC   8             /* j-columns per CTA in recurrence */
#define NCTA  (HID/JPC)     /* 128 persistent CTAs */
#define RPC   (4*JPC)       /* W_hh rows per CTA = 32 */

// ---------------------------------------------------------------------------
// Static device scratch
// ---------------------------------------------------------------------------
__device__ __half g_emb_hi[VOCAB*EMB];
__device__ __half g_emb_lo[VOCAB*EMB];
__device__ __half g_Wih_hi[GATES*EMB];
__device__ __half g_Wih_lo[GATES*EMB];
__device__ __half g_Whh_hi[GATES*HID];
__device__ __half g_Whh_lo[GATES*HID];
__device__ __half g_Wfc_hi[(size_t)VPAD*HID];
__device__ __half g_Wfc_lo[(size_t)VPAD*HID];
__device__ float  g_xg[(size_t)MROWS*GATES];
__device__ __half g_hs_hi[MROWS*HID];
__device__ __half g_h_hi[2][BATCH*HID];      // double-buffered h (fp16 hi only)

// sync state (reset by init_state each call; monotonic within a call)
__device__ unsigned g_ck[2][8];              // per-buffer per-chunk producer counts
__device__ unsigned g_arr_cnt;               // split-barrier arrivals (monotonic)
__device__ volatile unsigned g_gen;          // completed-arrival generations

// ---------------------------------------------------------------------------
// Prep
// ---------------------------------------------------------------------------
__device__ __forceinline__ void split1(float f, __half* hi, __half* lo, size_t i) {
    __half h = __float2half_rn(f);
    hi[i] = h;
    lo[i] = __float2half_rn(f - __half2float(h));
}

__global__ void prep_emb(const float* __restrict__ src) {
    for (int i = blockIdx.x*blockDim.x + threadIdx.x; i < VOCAB*EMB; i += gridDim.x*blockDim.x)
        split1(src[i], g_emb_hi, g_emb_lo, i);
}
__global__ void prep_wih(const float* __restrict__ src) {
    for (int i = blockIdx.x*blockDim.x + threadIdx.x; i < GATES*EMB; i += gridDim.x*blockDim.x)
        split1(src[i], g_Wih_hi, g_Wih_lo, i);
}
__global__ void prep_whh(const float* __restrict__ src) {
    for (int i = blockIdx.x*blockDim.x + threadIdx.x; i < GATES*HID; i += gridDim.x*blockDim.x)
        split1(src[i], g_Whh_hi, g_Whh_lo, i);
}
__global__ void prep_wfc(const float* __restrict__ src) {
    for (size_t i = blockIdx.x*blockDim.x + threadIdx.x; i < (size_t)VPAD*HID; i += (size_t)gridDim.x*blockDim.x) {
        float f = (i < (size_t)VOCAB*HID) ? src[i] : 0.0f;
        split1(f, g_Wfc_hi, g_Wfc_lo, i);
    }
}
__global__ void init_state() {
    int i = blockIdx.x*blockDim.x + threadIdx.x;
    if (i < BATCH*HID) g_h_hi[0][i] = __float2half_rn(0.0f);
    if (i == 0) { g_arr_cnt = 0u; g_gen = 0u; }
    if (i < 16) ((unsigned*)g_ck)[i] = 0u;
}

// ---------------------------------------------------------------------------
// Kernel 1: xg = emb[x] @ W_ih^T  (M=16384, N=4096, K=512), 3-pass hi/lo.
// 128x128 CTA tile, 256 threads (8 warps as 4x2), warp = 32x64 out. KC=32.
// ---------------------------------------------------------------------------
__global__ __launch_bounds__(256) void embed_gemm(const int* __restrict__ x) {
    __shared__ __align__(16) __half As_hi[128*40], As_lo[128*40];
    __shared__ __align__(16) __half Bs_hi[128*40], Bs_lo[128*40];
    __shared__ int rowidx[128];

    const int n0 = blockIdx.x * 128;
    const int m0 = blockIdx.y * 128;
    const int tid = threadIdx.x;
    const int warp = tid >> 5;
    const int wm = warp >> 1, wn = warp & 1;

    if (tid < 128) rowidx[tid] = x[m0 + tid];
    __syncthreads();

    wmma::fragment<wmma::accumulator, 16, 16, 16, float> acc[2][4];
    #pragma unroll
    for (int i = 0; i < 2; i++)
        #pragma unroll
        for (int j = 0; j < 4; j++)
            wmma::fill_fragment(acc[i][j], 0.0f);

    for (int k0 = 0; k0 < EMB; k0 += 32) {
        #pragma unroll
        for (int it = 0; it < 2; it++) {
            const int idx = tid + it*256;
            const int row = idx >> 2, c4 = idx & 3;
            const int r = rowidx[row];
            *(int4*)(As_hi + row*40 + c4*8) = *(const int4*)(g_emb_hi + (size_t)r*EMB + k0 + c4*8);
            *(int4*)(As_lo + row*40 + c4*8) = *(const int4*)(g_emb_lo + (size_t)r*EMB + k0 + c4*8);
            const int n = n0 + row;
            *(int4*)(Bs_hi + row*40 + c4*8) = *(const int4*)(g_Wih_hi + (size_t)n*EMB + k0 + c4*8);
            *(int4*)(Bs_lo + row*40 + c4*8) = *(const int4*)(g_Wih_lo + (size_t)n*EMB + k0 + c4*8);
        }
        __syncthreads();

        #pragma unroll
        for (int ks = 0; ks < 2; ks++) {
            wmma::fragment<wmma::matrix_a, 16, 16, 16, __half, wmma::row_major> a_hi[2], a_lo[2];
            wmma::fragment<wmma::matrix_b, 16, 16, 16, __half, wmma::col_major> b_hi[4], b_lo[4];
            #pragma unroll
            for (int i = 0; i < 2; i++) {
                wmma::load_matrix_sync(a_hi[i], As_hi + (wm*32 + i*16)*40 + ks*16, 40);
                wmma::load_matrix_sync(a_lo[i], As_lo + (wm*32 + i*16)*40 + ks*16, 40);
            }
            #pragma unroll
            for (int j = 0; j < 4; j++) {
                wmma::load_matrix_sync(b_hi[j], Bs_hi + (wn*64 + j*16)*40 + ks*16, 40);
                wmma::load_matrix_sync(b_lo[j], Bs_lo + (wn*64 + j*16)*40 + ks*16, 40);
            }
            #pragma unroll
            for (int i = 0; i < 2; i++)
                #pragma unroll
                for (int j = 0; j < 4; j++) {
                    wmma::mma_sync(acc[i][j], a_hi[i], b_hi[j], acc[i][j]);
                    wmma::mma_sync(acc[i][j], a_hi[i], b_lo[j], acc[i][j]);
                    wmma::mma_sync(acc[i][j], a_lo[i], b_hi[j], acc[i][j]);
                }
        }
        __syncthreads();
    }

    #pragma unroll
    for (int i = 0; i < 2; i++)
        #pragma unroll
        for (int j = 0; j < 4; j++)
            wmma::store_matrix_sync(
                g_xg + (size_t)(m0 + wm*32 + i*16)*GATES + n0 + wn*64 + j*16,
                acc[i][j], GATES, wmma::mem_row_major);
}

// ---------------------------------------------------------------------------
// Kernel 2: persistent LSTM recurrence, chunk-flag pipelined.
// 128 CTAs x 256 threads, CTA owns j-slice [j0,j0+8); 2-pass (h_hi only):
// gates = h_hi @ (W_hi + W_lo)^T.  8 warps in 2 k-groups of 4.
//
// Sync protocol (per step s, rb=s&1, wb=rb^1):
//  - consumer: before staging chunk c of g_h_hi[rb], spin until
//      g_ck[rb][c] >= 16*((s+1)>>1)   (16 producers per chunk per write-pass)
//  - after last g_h read of the step: one thread atomicAdd(g_arr_cnt);
//      the 128(s+1)-th arrival sets g_gen = s+1  (split-phase barrier arrive)
//  - producer: before writing h into g_h_hi[wb], spin until g_gen >= s
//      (all CTAs finished reading that buffer at step s-1)
//  - after h writes: threadfence + atomicAdd(g_ck[wb][blockIdx.x>>4])
// ---------------------------------------------------------------------------
#define SM_W    (RPC*1032)                    /* halves per W matrix */
#define SM_H    (2*2*32*136)                  /* grp, buf, 32, 136 halves */
#define SMEM_PERSIST ((2*SM_W + SM_H)*2 + (2*32*36 + 32*JPC + RPC)*4)

__global__ __launch_bounds__(256, 1) void lstm_persist(const float* __restrict__ b_ih,
                                                       const float* __restrict__ b_hh) {
    extern __shared__ __align__(16) char smraw[];
    __half* sWhi = (__half*)smraw;               // [32][1032]
    __half* sWlo = sWhi + SM_W;                  // [32][1032]
    __half* sH   = sWlo + SM_W;                  // [g][buf][32][136]
    float*  gsm  = (float*)(sH + SM_H);          // [2][32][36]
    float*  cst  = gsm + 2*32*36;                // [32][8]
    float*  bias = cst + 32*JPC;                 // [32]

    const int tid  = threadIdx.x;
    const int warp = tid >> 5;
    const int grp  = warp >> 2;                  // k-group 0/1
    const int w2   = warp & 3;
    const int wm = w2 >> 1, wn = w2 & 1;
    const int j0 = blockIdx.x * JPC;
    const int mychunk = blockIdx.x >> 4;         // h chunk this CTA produces into

    // Cache W_hh slice (hi+lo) once
    for (int i = tid; i < RPC*128; i += 256) {
        int r = i >> 7, ci = i & 127;
        int gr = (r >> 3)*HID + j0 + (r & 7);
        ((int4*)(sWhi + r*1032))[ci] = ((const int4*)(g_Whh_hi + (size_t)gr*HID))[ci];
        ((int4*)(sWlo + r*1032))[ci] = ((const int4*)(g_Whh_lo + (size_t)gr*HID))[ci];
    }
    if (tid < RPC) {
        int gr = (tid >> 3)*HID + j0 + (tid & 7);
        bias[tid] = b_ih[gr] + b_hh[gr];
    }
    for (int i = tid; i < BATCH*JPC; i += 256) cst[i] = 0.0f;
    __syncthreads();

    const int t4 = tid & 127;
    const int pb = t4 >> 2, pq = t4 & 3;         // loader: 32 rows x 4 int4
    volatile unsigned* vck = (volatile unsigned*)g_ck;

    for (int s = 0; s < SEQ; s++) {
        const int rb = s & 1, wb = rb ^ 1;
        const unsigned tgt = 16u * ((unsigned)(s + 1) >> 1);
        const __half* __restrict__ hc = g_h_hi[rb];
        __half* __restrict__ hn = g_h_hi[wb];

        // xg prefetch for this thread's cell update
        float xv[4];
        {
            const int b = tid >> 3;
            const float* xr = g_xg + (size_t)(b*SEQ + s)*GATES + j0 + (tid & 7);
            #pragma unroll
            for (int g = 0; g < 4; g++) xv[g] = __ldg(xr + g*HID);
        }

        wmma::fragment<wmma::accumulator, 16, 16, 16, float> accA, accB;
        wmma::fill_fragment(accA, 0.0f);
        wmma::fill_fragment(accB, 0.0f);

        // wait + prefetch this group's chunk 0
        int4 pf[4];
        {
            while (vck[rb*8 + grp*4] < tgt) __nanosleep(32);
            __threadfence();
            const int4* hi4 = (const int4*)(hc + pb*HID + grp*512);
            #pragma unroll
            for (int i = 0; i < 4; i++) pf[i] = hi4[pq + 4*i];
        }

        for (int ck = 0; ck < 4; ck++) {
            const int buf = ck & 1;
            __half* base = sH + ((grp*2 + buf)*32)*136;
            __syncthreads();
            {
                int4* d = (int4*)(base + pb*136);
                #pragma unroll
                for (int i = 0; i < 4; i++) d[pq + 4*i] = pf[i];
            }
            __syncthreads();
            if (ck < 3) {
                // wait + prefetch next chunk (overlaps MMA below)
                while (vck[rb*8 + grp*4 + ck + 1] < tgt) __nanosleep(32);
                __threadfence();
                const int4* hi4 = (const int4*)(hc + pb*HID + grp*512 + (ck + 1)*128);
                #pragma unroll
                for (int i = 0; i < 4; i++) pf[i] = hi4[pq + 4*i];
            } else {
                // all g_h reads of this step are done -> split-barrier arrive
                if (tid == 0) {
                    __threadfence();
                    if (atomicAdd(&g_arr_cnt, 1u) == (unsigned)NCTA*(unsigned)(s + 1) - 1u)
                        g_gen = (unsigned)(s + 1);
                }
            }
            #pragma unroll
            for (int ki = 0; ki < 8; ki++) {
                const int kg = grp*512 + ck*128 + ki*16;
                wmma::fragment<wmma::matrix_a, 16, 16, 16, __half, wmma::row_major> a_hi;
                wmma::fragment<wmma::matrix_b, 16, 16, 16, __half, wmma::col_major> b_hi, b_lo;
                wmma::load_matrix_sync(a_hi, base + (wm*16)*136 + ki*16, 136);
                wmma::load_matrix_sync(b_hi, sWhi + (wn*16)*1032 + kg, 1032);
                wmma::load_matrix_sync(b_lo, sWlo + (wn*16)*1032 + kg, 1032);
                wmma::mma_sync(accA, a_hi, b_hi, accA);
                wmma::mma_sync(accB, a_hi, b_lo, accB);
            }
        }
        #pragma unroll
        for (int i = 0; i < accA.num_elements; i++) accA.x[i] += accB.x[i];

        wmma::store_matrix_sync(gsm + grp*32*36 + (wm*16)*36 + wn*16, accA, 36,
                                wmma::mem_row_major);
        __syncthreads();

        // fused cell update: one output per thread (32 batch x 8 j)
        {
            const int b  = tid >> 3;
            const int jj = tid & 7;
            const int j  = j0 + jj;
            float iv = gsm[b*36 +  0 + jj] + gsm[32*36 + b*36 +  0 + jj] + xv[0] + bias[ 0 + jj];
            float fv = gsm[b*36 +  8 + jj] + gsm[32*36 + b*36 +  8 + jj] + xv[1] + bias[ 8 + jj];
            float gv = gsm[b*36 + 16 + jj] + gsm[32*36 + b*36 + 16 + jj] + xv[2] + bias[16 + jj];
            float ov = gsm[b*36 + 24 + jj] + gsm[32*36 + b*36 + 24 + jj] + xv[3] + bias[24 + jj];

            float ig = 1.0f / (1.0f + expf(-iv));
            float fg = 1.0f / (1.0f + expf(-fv));
            float gg = tanhf(gv);
            float og = 1.0f / (1.0f + expf(-ov));

            float c = fg * cst[b*JPC + jj] + ig * gg;
            cst[b*JPC + jj] = c;
            float h = og * tanhf(c);
            __half hh = __float2half_rn(h);

            // producer gate: everyone must have finished reading buffer wb
            while (g_gen < (unsigned)s) __nanosleep(32);
            __threadfence();

            hn[b*HID + j] = hh;
            g_hs_hi[(size_t)(b*SEQ + s)*HID + j] = hh;
        }
        __syncthreads();
        if (tid == 0) {
            __threadfence();
            atomicAdd(&g_ck[wb][mychunk], 1u);
        }
    }
}

// ---------------------------------------------------------------------------
// Kernel 3: logits = hs @ W_fc^T + b_fc  (M=16384, N=5120pad, K=1024)
// 128x128 tile, 256 threads, 2-pass (a_hi*b_hi + a_hi*b_lo), KC=32.
// ---------------------------------------------------------------------------
__global__ __launch_bounds__(256) void fc_gemm(const float* __restrict__ b_fc,
                                               float* __restrict__ out) {
    __shared__ __align__(16) __half As_hi[128*40];
    __shared__ __align__(16) __half Bs_hi[128*40], Bs_lo[128*40];
    __shared__ __align__(32) float  Cw[8][16*24];

    const int n0 = blockIdx.x * 128;
    const int m0 = blockIdx.y * 128;
    const int tid = threadIdx.x;
    const int warp = tid >> 5;
    const int lane = tid & 31;
    const int wm = warp >> 1, wn = warp & 1;

    wmma::fragment<wmma::accumulator, 16, 16, 16, float> acc[2][4];
    #pragma unroll
    for (int i = 0; i < 2; i++)
        #pragma unroll
        for (int j = 0; j < 4; j++)
            wmma::fill_fragment(acc[i][j], 0.0f);

    for (int k0 = 0; k0 < HID; k0 += 32) {
        #pragma unroll
        for (int it = 0; it < 2; it++) {
            const int idx = tid + it*256;
            const int row = idx >> 2, c4 = idx & 3;
            *(int4*)(As_hi + row*40 + c4*8) = *(const int4*)(g_hs_hi + (size_t)(m0 + row)*HID + k0 + c4*8);
            const int n = n0 + row;
            *(int4*)(Bs_hi + row*40 + c4*8) = *(const int4*)(g_Wfc_hi + (size_t)n*HID + k0 + c4*8);
            *(int4*)(Bs_lo + row*40 + c4*8) = *(const int4*)(g_Wfc_lo + (size_t)n*HID + k0 + c4*8);
        }
        __syncthreads();

        #pragma unroll
        for (int ks = 0; ks < 2; ks++) {
            wmma::fragment<wmma::matrix_a, 16, 16, 16, __half, wmma::row_major> a_hi[2];
            wmma::fragment<wmma::matrix_b, 16, 16, 16, __half, wmma::col_major> b_hi[4], b_lo[4];
            #pragma unroll
            for (int i = 0; i < 2; i++)
                wmma::load_matrix_sync(a_hi[i], As_hi + (wm*32 + i*16)*40 + ks*16, 40);
            #pragma unroll
            for (int j = 0; j < 4; j++) {
                wmma::load_matrix_sync(b_hi[j], Bs_hi + (wn*64 + j*16)*40 + ks*16, 40);
                wmma::load_matrix_sync(b_lo[j], Bs_lo + (wn*64 + j*16)*40 + ks*16, 40);
            }
            #pragma unroll
            for (int i = 0; i < 2; i++)
                #pragma unroll
                for (int j = 0; j < 4; j++) {
                    wmma::mma_sync(acc[i][j], a_hi[i], b_hi[j], acc[i][j]);
                    wmma::mma_sync(acc[i][j], a_hi[i], b_lo[j], acc[i][j]);
                }
        }
        __syncthreads();
    }

    #pragma unroll
    for (int i = 0; i < 2; i++)
        #pragma unroll
        for (int j = 0; j < 4; j++) {
            __syncwarp();
            wmma::store_matrix_sync(Cw[warp], acc[i][j], 24, wmma::mem_row_major);
            __syncwarp();
            const int mbase = m0 + wm*32 + i*16;
            const int nbase = n0 + wn*64 + j*16;
            #pragma unroll
            for (int e = 0; e < 8; e++) {
                const int idx = lane*8 + e;
                const int rr = idx >> 4, cc = idx & 15;
                const int v = nbase + cc;
                if (v < VOCAB)
                    out[(size_t)(mbase + rr)*VOCAB + v] = Cw[warp][rr*24 + cc] + b_fc[v];
            }
        }
}

// ---------------------------------------------------------------------------
// Launch
// ---------------------------------------------------------------------------
extern "C" void kernel_launch(void* const* d_in, const int* in_sizes, int n_in,
                              void* d_out, int out_size) {
    const int*   x    = (const int*)  d_in[0];
    const float* emb  = (const float*)d_in[1];
    const float* W_ih = (const float*)d_in[2];
    const float* W_hh = (const float*)d_in[3];
    const float* b_ih = (const float*)d_in[4];
    const float* b_hh = (const float*)d_in[5];
    const float* W_fc = (const float*)d_in[6];
    const float* b_fc = (const float*)d_in[7];
    float* out = (float*)d_out;

    (void)in_sizes; (void)n_in; (void)out_size;

    prep_emb<<<512, 256>>>(emb);
    prep_wih<<<512, 256>>>(W_ih);
    prep_whh<<<512, 256>>>(W_hh);
    prep_wfc<<<512, 256>>>(W_fc);
    init_state<<<(BATCH*HID + 255)/256, 256>>>();

    embed_gemm<<<dim3(GATES/128, MROWS/128), 256>>>(x);

    cudaFuncSetAttribute(lstm_persist, cudaFuncAttributeMaxDynamicSharedMemorySize,
                         SMEM_PERSIST);
    lstm_persist<<<NCTA, 256, SMEM_PERSIST>>>(b_ih, b_hh);

    fc_gemm<<<dim3(VPAD/128, MROWS/128), 256>>>(b_fc, out);
}

// round 7
// speedup vs baseline: 1.2053x; 1.2053x over previous
#include <cuda_runtime.h>
#include <cuda_fp16.h>
#include <mma.h>
#include <math.h>

using namespace nvcuda;

#define VOCAB 5000
#define EMB   512
#define HID   1024
#define GATES 4096
#define BATCH 32
#define SEQ   512
#define MROWS (BATCH*SEQ)   /* 16384 */
#define VPAD  5120          /* 40 * 128 */

#define JPC   8             /* j-columns per CTA in recurrence */
#define NCTA  (HID/JPC)     /* 128 persistent CTAs */
#define RPC   (4*JPC)       /* W_hh rows per CTA = 32 */

// ---------------------------------------------------------------------------
// Static device scratch
// ---------------------------------------------------------------------------
__device__ __half g_emb_hi[VOCAB*EMB];
__device__ __half g_emb_lo[VOCAB*EMB];
__device__ __half g_Wih_hi[GATES*EMB];
__device__ __half g_Wih_lo[GATES*EMB];
__device__ __half g_Whh_hi[GATES*HID];
__device__ __half g_Whh_lo[GATES*HID];
__device__ __half g_Wfc_hi[(size_t)VPAD*HID];
__device__ __half g_Wfc_lo[(size_t)VPAD*HID];
__device__ float  g_xg[(size_t)MROWS*GATES];
__device__ __half g_hs_hi[MROWS*HID];
__device__ __half g_h_hi[2][BATCH*HID];      // double-buffered h (fp16 hi only)

// hierarchical barrier state (reset by init_state; monotonic within a call)
__device__ unsigned g_cnt[8*64];             // 8 counters, 256B apart
__device__ unsigned g_master;
__device__ volatile unsigned g_gen;

// ---------------------------------------------------------------------------
// Prep
// ---------------------------------------------------------------------------
__device__ __forceinline__ void split1(float f, __half* hi, __half* lo, size_t i) {
    __half h = __float2half_rn(f);
    hi[i] = h;
    lo[i] = __float2half_rn(f - __half2float(h));
}

__global__ void prep_emb(const float* __restrict__ src) {
    for (int i = blockIdx.x*blockDim.x + threadIdx.x; i < VOCAB*EMB; i += gridDim.x*blockDim.x)
        split1(src[i], g_emb_hi, g_emb_lo, i);
}
__global__ void prep_wih(const float* __restrict__ src) {
    for (int i = blockIdx.x*blockDim.x + threadIdx.x; i < GATES*EMB; i += gridDim.x*blockDim.x)
        split1(src[i], g_Wih_hi, g_Wih_lo, i);
}
__global__ void prep_whh(const float* __restrict__ src) {
    for (int i = blockIdx.x*blockDim.x + threadIdx.x; i < GATES*HID; i += gridDim.x*blockDim.x)
        split1(src[i], g_Whh_hi, g_Whh_lo, i);
}
__global__ void prep_wfc(const float* __restrict__ src) {
    for (size_t i = blockIdx.x*blockDim.x + threadIdx.x; i < (size_t)VPAD*HID; i += (size_t)gridDim.x*blockDim.x) {
        float f = (i < (size_t)VOCAB*HID) ? src[i] : 0.0f;
        split1(f, g_Wfc_hi, g_Wfc_lo, i);
    }
}
__global__ void init_state() {
    int i = blockIdx.x*blockDim.x + threadIdx.x;
    if (i < BATCH*HID) g_h_hi[0][i] = __float2half_rn(0.0f);
    if (i < 8*64) g_cnt[i] = 0u;
    if (i == 0) { g_master = 0u; g_gen = 0u; }
}

// ---------------------------------------------------------------------------
// Kernel 1: xg = emb[x] @ W_ih^T  (M=16384, N=4096, K=512), 3-pass hi/lo.
// 128x128 CTA tile, 256 threads (8 warps as 4x2), warp = 32x64 out. KC=32.
// ---------------------------------------------------------------------------
__global__ __launch_bounds__(256) void embed_gemm(const int* __restrict__ x) {
    __shared__ __align__(16) __half As_hi[128*40], As_lo[128*40];
    __shared__ __align__(16) __half Bs_hi[128*40], Bs_lo[128*40];
    __shared__ int rowidx[128];

    const int n0 = blockIdx.x * 128;
    const int m0 = blockIdx.y * 128;
    const int tid = threadIdx.x;
    const int warp = tid >> 5;
    const int wm = warp >> 1, wn = warp & 1;

    if (tid < 128) rowidx[tid] = x[m0 + tid];
    __syncthreads();

    wmma::fragment<wmma::accumulator, 16, 16, 16, float> acc[2][4];
    #pragma unroll
    for (int i = 0; i < 2; i++)
        #pragma unroll
        for (int j = 0; j < 4; j++)
            wmma::fill_fragment(acc[i][j], 0.0f);

    for (int k0 = 0; k0 < EMB; k0 += 32) {
        #pragma unroll
        for (int it = 0; it < 2; it++) {
            const int idx = tid + it*256;
            const int row = idx >> 2, c4 = idx & 3;
            const int r = rowidx[row];
            *(int4*)(As_hi + row*40 + c4*8) = *(const int4*)(g_emb_hi + (size_t)r*EMB + k0 + c4*8);
            *(int4*)(As_lo + row*40 + c4*8) = *(const int4*)(g_emb_lo + (size_t)r*EMB + k0 + c4*8);
            const int n = n0 + row;
            *(int4*)(Bs_hi + row*40 + c4*8) = *(const int4*)(g_Wih_hi + (size_t)n*EMB + k0 + c4*8);
            *(int4*)(Bs_lo + row*40 + c4*8) = *(const int4*)(g_Wih_lo + (size_t)n*EMB + k0 + c4*8);
        }
        __syncthreads();

        #pragma unroll
        for (int ks = 0; ks < 2; ks++) {
            wmma::fragment<wmma::matrix_a, 16, 16, 16, __half, wmma::row_major> a_hi[2], a_lo[2];
            wmma::fragment<wmma::matrix_b, 16, 16, 16, __half, wmma::col_major> b_hi[4], b_lo[4];
            #pragma unroll
            for (int i = 0; i < 2; i++) {
                wmma::load_matrix_sync(a_hi[i], As_hi + (wm*32 + i*16)*40 + ks*16, 40);
                wmma::load_matrix_sync(a_lo[i], As_lo + (wm*32 + i*16)*40 + ks*16, 40);
            }
            #pragma unroll
            for (int j = 0; j < 4; j++) {
                wmma::load_matrix_sync(b_hi[j], Bs_hi + (wn*64 + j*16)*40 + ks*16, 40);
                wmma::load_matrix_sync(b_lo[j], Bs_lo + (wn*64 + j*16)*40 + ks*16, 40);
            }
            #pragma unroll
            for (int i = 0; i < 2; i++)
                #pragma unroll
                for (int j = 0; j < 4; j++) {
                    wmma::mma_sync(acc[i][j], a_hi[i], b_hi[j], acc[i][j]);
                    wmma::mma_sync(acc[i][j], a_hi[i], b_lo[j], acc[i][j]);
                    wmma::mma_sync(acc[i][j], a_lo[i], b_hi[j], acc[i][j]);
                }
        }
        __syncthreads();
    }

    #pragma unroll
    for (int i = 0; i < 2; i++)
        #pragma unroll
        for (int j = 0; j < 4; j++)
            wmma::store_matrix_sync(
                g_xg + (size_t)(m0 + wm*32 + i*16)*GATES + n0 + wn*64 + j*16,
                acc[i][j], GATES, wmma::mem_row_major);
}

// ---------------------------------------------------------------------------
// Hierarchical grid barrier: 8 spread arrival counters -> master -> g_gen.
// tid0-only polling (R6 lesson: never poll from all threads).
// ---------------------------------------------------------------------------
__device__ __forceinline__ void grid_barrier(int s) {
    __syncthreads();
    if (threadIdx.x == 0) {
        __threadfence();
        const unsigned c = blockIdx.x & 7u;
        if (atomicAdd(&g_cnt[c*64], 1u) == 16u*(unsigned)(s + 1) - 1u) {
            if (atomicAdd(&g_master, 1u) == 8u*(unsigned)(s + 1) - 1u) {
                __threadfence();
                g_gen = (unsigned)(s + 1);
            }
        }
        while (g_gen < (unsigned)(s + 1)) __nanosleep(32);
        __threadfence();
    }
    __syncthreads();
}

// ---------------------------------------------------------------------------
// Kernel 2: persistent LSTM recurrence. 128 CTAs x 256 threads.
// CTA owns j-slice [j0,j0+8); W_hh slice (hi+lo) cached in smem.
// 2-pass, h_hi only: gates = h_hi @ (W_hi + W_lo)^T.
// 8 warps in 2 k-groups of 4; per step ONE staging phase loads the whole
// 32x512 h slice per group into smem (2 syncthreads/step total), then
// 32 k-iters of MMA. Hierarchical barrier at end of step.
// ---------------------------------------------------------------------------
#define SM_W     (RPC*1032)                   /* halves per W matrix: 33024 */
#define SM_HROW  520
#define SM_H     (2*32*SM_HROW)               /* 2 groups x 32 x 520 halves */
#define SMEM_PERSIST ((2*SM_W + SM_H)*2 + (2*32*36 + 32*JPC + RPC)*4)

__global__ __launch_bounds__(256, 1) void lstm_persist(const float* __restrict__ b_ih,
                                                       const float* __restrict__ b_hh) {
    extern __shared__ __align__(16) char smraw[];
    __half* sWhi = (__half*)smraw;               // [32][1032]
    __half* sWlo = sWhi + SM_W;                  // [32][1032]
    __half* sH   = sWlo + SM_W;                  // [g][32][520]
    float*  gsm  = (float*)(sH + SM_H);          // [2][32][36]
    float*  cst  = gsm + 2*32*36;                // [32][8]
    float*  bias = cst + 32*JPC;                 // [32]

    const int tid  = threadIdx.x;
    const int warp = tid >> 5;
    const int grp  = warp >> 2;                  // k-group 0/1
    const int w2   = warp & 3;
    const int wm = w2 >> 1, wn = w2 & 1;
    const int j0 = blockIdx.x * JPC;

    // Cache W_hh slice (hi+lo) once
    for (int i = tid; i < RPC*128; i += 256) {
        int r = i >> 7, ci = i & 127;
        int gr = (r >> 3)*HID + j0 + (r & 7);
        ((int4*)(sWhi + r*1032))[ci] = ((const int4*)(g_Whh_hi + (size_t)gr*HID))[ci];
        ((int4*)(sWlo + r*1032))[ci] = ((const int4*)(g_Whh_lo + (size_t)gr*HID))[ci];
    }
    if (tid < RPC) {
        int gr = (tid >> 3)*HID + j0 + (tid & 7);
        bias[tid] = b_ih[gr] + b_hh[gr];
    }
    for (int i = tid; i < BATCH*JPC; i += 256) cst[i] = 0.0f;
    __syncthreads();

    // h loader mapping: 64 rows (2 grp x 32 batch), 4 threads/row, 16 int4 each
    const int lrow = tid >> 2;                   // 0..63
    const int lgrp = lrow >> 5, lb = lrow & 31;
    const int lq = tid & 3;

    for (int s = 0; s < SEQ; s++) {
        const int rb = s & 1, wb = rb ^ 1;
        const __half* __restrict__ hc = g_h_hi[rb];
        __half* __restrict__ hn = g_h_hi[wb];

        // xg prefetch for this thread's cell update (hides DRAM latency)
        float xv[4];
        {
            const int b = tid >> 3;
            const float* xr = g_xg + (size_t)(b*SEQ + s)*GATES + j0 + (tid & 7);
            #pragma unroll
            for (int g = 0; g < 4; g++) xv[g] = __ldg(xr + g*HID);
        }

        // single-shot staging of both h group slices (32x512 halves each)
        {
            const int4* src = (const int4*)(hc + lb*HID + lgrp*512);
            int4* dst = (int4*)(sH + (lgrp*32 + lb)*SM_HROW);
            #pragma unroll
            for (int i = 0; i < 16; i++) dst[lq + 4*i] = src[lq + 4*i];
        }
        __syncthreads();

        wmma::fragment<wmma::accumulator, 16, 16, 16, float> accA, accB;
        wmma::fill_fragment(accA, 0.0f);
        wmma::fill_fragment(accB, 0.0f);

        const __half* aBase = sH + (grp*32 + wm*16)*SM_HROW;
        const __half* bhBase = sWhi + (wn*16)*1032 + grp*512;
        const __half* blBase = sWlo + (wn*16)*1032 + grp*512;
        #pragma unroll
        for (int ki = 0; ki < 32; ki++) {
            wmma::fragment<wmma::matrix_a, 16, 16, 16, __half, wmma::row_major> a_hi;
            wmma::fragment<wmma::matrix_b, 16, 16, 16, __half, wmma::col_major> b_hi, b_lo;
            wmma::load_matrix_sync(a_hi, aBase + ki*16, SM_HROW);
            wmma::load_matrix_sync(b_hi, bhBase + ki*16, 1032);
            wmma::load_matrix_sync(b_lo, blBase + ki*16, 1032);
            wmma::mma_sync(accA, a_hi, b_hi, accA);
            wmma::mma_sync(accB, a_hi, b_lo, accB);
        }
        #pragma unroll
        for (int i = 0; i < accA.num_elements; i++) accA.x[i] += accB.x[i];

        wmma::store_matrix_sync(gsm + grp*32*36 + (wm*16)*36 + wn*16, accA, 36,
                                wmma::mem_row_major);
        __syncthreads();

        // fused cell update: one output per thread (32 batch x 8 j)
        {
            const int b  = tid >> 3;
            const int jj = tid & 7;
            const int j  = j0 + jj;
            float iv = gsm[b*36 +  0 + jj] + gsm[32*36 + b*36 +  0 + jj] + xv[0] + bias[ 0 + jj];
            float fv = gsm[b*36 +  8 + jj] + gsm[32*36 + b*36 +  8 + jj] + xv[1] + bias[ 8 + jj];
            float gv = gsm[b*36 + 16 + jj] + gsm[32*36 + b*36 + 16 + jj] + xv[2] + bias[16 + jj];
            float ov = gsm[b*36 + 24 + jj] + gsm[32*36 + b*36 + 24 + jj] + xv[3] + bias[24 + jj];

            float ig = 1.0f / (1.0f + expf(-iv));
            float fg = 1.0f / (1.0f + expf(-fv));
            float gg = tanhf(gv);
            float og = 1.0f / (1.0f + expf(-ov));

            float c = fg * cst[b*JPC + jj] + ig * gg;
            cst[b*JPC + jj] = c;
            float h = og * tanhf(c);
            __half hh = __float2half_rn(h);

            hn[b*HID + j] = hh;
            g_hs_hi[(size_t)(b*SEQ + s)*HID + j] = hh;
        }
        grid_barrier(s);
    }
}

// ---------------------------------------------------------------------------
// Kernel 3: logits = hs @ W_fc^T + b_fc  (M=16384, N=5120pad, K=1024)
// 128x128 tile, 256 threads, 2-pass (a_hi*b_hi + a_hi*b_lo), KC=32.
// ---------------------------------------------------------------------------
__global__ __launch_bounds__(256) void fc_gemm(const float* __restrict__ b_fc,
                                               float* __restrict__ out) {
    __shared__ __align__(16) __half As_hi[128*40];
    __shared__ __align__(16) __half Bs_hi[128*40], Bs_lo[128*40];
    __shared__ __align__(32) float  Cw[8][16*24];

    const int n0 = blockIdx.x * 128;
    const int m0 = blockIdx.y * 128;
    const int tid = threadIdx.x;
    const int warp = tid >> 5;
    const int lane = tid & 31;
    const int wm = warp >> 1, wn = warp & 1;

    wmma::fragment<wmma::accumulator, 16, 16, 16, float> acc[2][4];
    #pragma unroll
    for (int i = 0; i < 2; i++)
        #pragma unroll
        for (int j = 0; j < 4; j++)
            wmma::fill_fragment(acc[i][j], 0.0f);

    for (int k0 = 0; k0 < HID; k0 += 32) {
        #pragma unroll
        for (int it = 0; it < 2; it++) {
            const int idx = tid + it*256;
            const int row = idx >> 2, c4 = idx & 3;
            *(int4*)(As_hi + row*40 + c4*8) = *(const int4*)(g_hs_hi + (size_t)(m0 + row)*HID + k0 + c4*8);
            const int n = n0 + row;
            *(int4*)(Bs_hi + row*40 + c4*8) = *(const int4*)(g_Wfc_hi + (size_t)n*HID + k0 + c4*8);
            *(int4*)(Bs_lo + row*40 + c4*8) = *(const int4*)(g_Wfc_lo + (size_t)n*HID + k0 + c4*8);
        }
        __syncthreads();

        #pragma unroll
        for (int ks = 0; ks < 2; ks++) {
            wmma::fragment<wmma::matrix_a, 16, 16, 16, __half, wmma::row_major> a_hi[2];
            wmma::fragment<wmma::matrix_b, 16, 16, 16, __half, wmma::col_major> b_hi[4], b_lo[4];
            #pragma unroll
            for (int i = 0; i < 2; i++)
                wmma::load_matrix_sync(a_hi[i], As_hi + (wm*32 + i*16)*40 + ks*16, 40);
            #pragma unroll
            for (int j = 0; j < 4; j++) {
                wmma::load_matrix_sync(b_hi[j], Bs_hi + (wn*64 + j*16)*40 + ks*16, 40);
                wmma::load_matrix_sync(b_lo[j], Bs_lo + (wn*64 + j*16)*40 + ks*16, 40);
            }
            #pragma unroll
            for (int i = 0; i < 2; i++)
                #pragma unroll
                for (int j = 0; j < 4; j++) {
                    wmma::mma_sync(acc[i][j], a_hi[i], b_hi[j], acc[i][j]);
                    wmma::mma_sync(acc[i][j], a_hi[i], b_lo[j], acc[i][j]);
                }
        }
        __syncthreads();
    }

    #pragma unroll
    for (int i = 0; i < 2; i++)
        #pragma unroll
        for (int j = 0; j < 4; j++) {
            __syncwarp();
            wmma::store_matrix_sync(Cw[warp], acc[i][j], 24, wmma::mem_row_major);
            __syncwarp();
            const int mbase = m0 + wm*32 + i*16;
            const int nbase = n0 + wn*64 + j*16;
            #pragma unroll
            for (int e = 0; e < 8; e++) {
                const int idx = lane*8 + e;
                const int rr = idx >> 4, cc = idx & 15;
                const int v = nbase + cc;
                if (v < VOCAB)
                    out[(size_t)(mbase + rr)*VOCAB + v] = Cw[warp][rr*24 + cc] + b_fc[v];
            }
        }
}

// ---------------------------------------------------------------------------
// Launch
// ---------------------------------------------------------------------------
extern "C" void kernel_launch(void* const* d_in, const int* in_sizes, int n_in,
                              void* d_out, int out_size) {
    const int*   x    = (const int*)  d_in[0];
    const float* emb  = (const float*)d_in[1];
    const float* W_ih = (const float*)d_in[2];
    const float* W_hh = (const float*)d_in[3];
    const float* b_ih = (const float*)d_in[4];
    const float* b_hh = (const float*)d_in[5];
    const float* W_fc = (const float*)d_in[6];
    const float* b_fc = (const float*)d_in[7];
    float* out = (float*)d_out;

    (void)in_sizes; (void)n_in; (void)out_size;

    prep_emb<<<512, 256>>>(emb);
    prep_wih<<<512, 256>>>(W_ih);
    prep_whh<<<512, 256>>>(W_hh);
    prep_wfc<<<512, 256>>>(W_fc);
    init_state<<<(BATCH*HID + 511)/512, 512>>>();

    embed_gemm<<<dim3(GATES/128, MROWS/128), 256>>>(x);

    cudaFuncSetAttribute(lstm_persist, cudaFuncAttributeMaxDynamicSharedMemorySize,
                         SMEM_PERSIST);
    lstm_persist<<<NCTA, 256, SMEM_PERSIST>>>(b_ih, b_hh);

    fc_gemm<<<dim3(VPAD/128, MROWS/128), 256>>>(b_fc, out);
}

// round 9
// speedup vs baseline: 1.4719x; 1.2212x over previous
#include <cuda_runtime.h>
#include <cuda_fp16.h>
#include <cuda_pipeline.h>
#include <mma.h>
#include <math.h>

using namespace nvcuda;

#define VOCAB 5000
#define EMB   512
#define HID   1024
#define GATES 4096
#define BATCH 32
#define SEQ   512
#define MROWS (BATCH*SEQ)   /* 16384 */
#define VPAD  5120          /* 40 * 128 */

#define JPC   8             /* j-columns per CTA in recurrence */
#define NCTA  (HID/JPC)     /* 128 persistent CTAs */
#define RPC   (4*JPC)       /* W_hh rows per CTA = 32 */

// ---------------------------------------------------------------------------
// Static device scratch
// ---------------------------------------------------------------------------
__device__ __half g_emb_hi[VOCAB*EMB];
__device__ __half g_emb_lo[VOCAB*EMB];
__device__ __half g_Wih_hi[GATES*EMB];
__device__ __half g_Wih_lo[GATES*EMB];
__device__ __half g_Whh_hi[GATES*HID];
__device__ __half g_Wfc_hi[(size_t)VPAD*HID];
__device__ __half g_Wfc_lo[(size_t)VPAD*HID];
__device__ float  g_xg[(size_t)MROWS*GATES];
__device__ __half g_hs_hi[MROWS*HID];
__device__ __half g_h_hi[2][BATCH*HID];      // double-buffered h (fp16 hi only)

// hierarchical barrier state (reset by init_state; monotonic within a call)
__device__ unsigned g_cnt[8*64];             // 8 counters, 256B apart
__device__ unsigned g_master;
__device__ volatile unsigned g_gen;

// ---------------------------------------------------------------------------
// Prep
// ---------------------------------------------------------------------------
__device__ __forceinline__ void split1(float f, __half* hi, __half* lo, size_t i) {
    __half h = __float2half_rn(f);
    hi[i] = h;
    lo[i] = __float2half_rn(f - __half2float(h));
}

__global__ void prep_emb(const float* __restrict__ src) {
    for (int i = blockIdx.x*blockDim.x + threadIdx.x; i < VOCAB*EMB; i += gridDim.x*blockDim.x)
        split1(src[i], g_emb_hi, g_emb_lo, i);
}
__global__ void prep_wih(const float* __restrict__ src) {
    for (int i = blockIdx.x*blockDim.x + threadIdx.x; i < GATES*EMB; i += gridDim.x*blockDim.x)
        split1(src[i], g_Wih_hi, g_Wih_lo, i);
}
__global__ void prep_whh(const float* __restrict__ src) {
    for (int i = blockIdx.x*blockDim.x + threadIdx.x; i < GATES*HID; i += gridDim.x*blockDim.x)
        g_Whh_hi[i] = __float2half_rn(src[i]);
}
__global__ void prep_wfc(const float* __restrict__ src) {
    for (size_t i = blockIdx.x*blockDim.x + threadIdx.x; i < (size_t)VPAD*HID; i += (size_t)gridDim.x*blockDim.x) {
        float f = (i < (size_t)VOCAB*HID) ? src[i] : 0.0f;
        split1(f, g_Wfc_hi, g_Wfc_lo, i);
    }
}
__global__ void init_state() {
    int i = blockIdx.x*blockDim.x + threadIdx.x;
    if (i < BATCH*HID) g_h_hi[0][i] = __float2half_rn(0.0f);
    if (i < 8*64) g_cnt[i] = 0u;
    if (i == 0) { g_master = 0u; g_gen = 0u; }
}

// ---------------------------------------------------------------------------
// Kernel 1: xg = emb[x] @ W_ih^T  (M=16384, N=4096, K=512), 3-pass hi/lo.
// 128x128 CTA tile, 256 threads, warp = 32x64. KC=32, 2-stage cp.async.
// ---------------------------------------------------------------------------
#define EG_STG 5120                       /* halves per array per stage */
#define EG_SMEM (8*EG_STG*2 + 128*4)

__global__ __launch_bounds__(256) void embed_gemm(const int* __restrict__ x) {
    extern __shared__ __align__(16) char sm[];
    __half* As_hi = (__half*)sm;                 // [2][5120]
    __half* As_lo = As_hi + 2*EG_STG;
    __half* Bs_hi = As_lo + 2*EG_STG;
    __half* Bs_lo = Bs_hi + 2*EG_STG;
    int*    rowidx = (int*)(Bs_lo + 2*EG_STG);

    const int n0 = blockIdx.x * 128;
    const int m0 = blockIdx.y * 128;
    const int tid = threadIdx.x;
    const int warp = tid >> 5;
    const int wm = warp >> 1, wn = warp & 1;

    if (tid < 128) rowidx[tid] = x[m0 + tid];
    __syncthreads();

    wmma::fragment<wmma::accumulator, 16, 16, 16, float> acc[2][4];
    #pragma unroll
    for (int i = 0; i < 2; i++)
        #pragma unroll
        for (int j = 0; j < 4; j++)
            wmma::fill_fragment(acc[i][j], 0.0f);

    auto issue = [&](int st, int k0) {
        const int so = st*EG_STG;
        #pragma unroll
        for (int it = 0; it < 2; it++) {
            const int idx = tid + it*256;
            const int row = idx >> 2, c8 = (idx & 3) * 8;
            const int r = rowidx[row];
            __pipeline_memcpy_async(As_hi + so + row*40 + c8, g_emb_hi + (size_t)r*EMB + k0 + c8, 16);
            __pipeline_memcpy_async(As_lo + so + row*40 + c8, g_emb_lo + (size_t)r*EMB + k0 + c8, 16);
            const int n = n0 + row;
            __pipeline_memcpy_async(Bs_hi + so + row*40 + c8, g_Wih_hi + (size_t)n*EMB + k0 + c8, 16);
            __pipeline_memcpy_async(Bs_lo + so + row*40 + c8, g_Wih_lo + (size_t)n*EMB + k0 + c8, 16);
        }
        __pipeline_commit();
    };

    auto compute = [&](int st) {
        const int so = st*EG_STG;
        #pragma unroll
        for (int ks = 0; ks < 2; ks++) {
            wmma::fragment<wmma::matrix_a, 16, 16, 16, __half, wmma::row_major> a_hi[2], a_lo[2];
            wmma::fragment<wmma::matrix_b, 16, 16, 16, __half, wmma::col_major> b_hi[4], b_lo[4];
            #pragma unroll
            for (int i = 0; i < 2; i++) {
                wmma::load_matrix_sync(a_hi[i], As_hi + so + (wm*32 + i*16)*40 + ks*16, 40);
                wmma::load_matrix_sync(a_lo[i], As_lo + so + (wm*32 + i*16)*40 + ks*16, 40);
            }
            #pragma unroll
            for (int j = 0; j < 4; j++) {
                wmma::load_matrix_sync(b_hi[j], Bs_hi + so + (wn*64 + j*16)*40 + ks*16, 40);
                wmma::load_matrix_sync(b_lo[j], Bs_lo + so + (wn*64 + j*16)*40 + ks*16, 40);
            }
            #pragma unroll
            for (int i = 0; i < 2; i++)
                #pragma unroll
                for (int j = 0; j < 4; j++) {
                    wmma::mma_sync(acc[i][j], a_hi[i], b_hi[j], acc[i][j]);
                    wmma::mma_sync(acc[i][j], a_hi[i], b_lo[j], acc[i][j]);
                    wmma::mma_sync(acc[i][j], a_lo[i], b_hi[j], acc[i][j]);
                }
        }
    };

    issue(0, 0);
    #pragma unroll 1
    for (int kc = 0; kc < EMB/32 - 1; kc++) {
        issue((kc + 1) & 1, (kc + 1)*32);
        __pipeline_wait_prior(1);
        __syncthreads();
        compute(kc & 1);
        __syncthreads();
    }
    __pipeline_wait_prior(0);
    __syncthreads();
    compute((EMB/32 - 1) & 1);

    #pragma unroll
    for (int i = 0; i < 2; i++)
        #pragma unroll
        for (int j = 0; j < 4; j++)
            wmma::store_matrix_sync(
                g_xg + (size_t)(m0 + wm*32 + i*16)*GATES + n0 + wn*64 + j*16,
                acc[i][j], GATES, wmma::mem_row_major);
}

// ---------------------------------------------------------------------------
// Hierarchical grid barrier (tid0-only polling)
// ---------------------------------------------------------------------------
__device__ __forceinline__ void grid_barrier(int s) {
    __syncthreads();
    if (threadIdx.x == 0) {
        __threadfence();
        const unsigned c = blockIdx.x & 7u;
        if (atomicAdd(&g_cnt[c*64], 1u) == 16u*(unsigned)(s + 1) - 1u) {
            if (atomicAdd(&g_master, 1u) == 8u*(unsigned)(s + 1) - 1u) {
                __threadfence();
                g_gen = (unsigned)(s + 1);
            }
        }
        while (g_gen < (unsigned)(s + 1)) __nanosleep(32);
        __threadfence();
    }
    __syncthreads();
}

// ---------------------------------------------------------------------------
// Kernel 2: persistent LSTM recurrence. 128 CTAs x 256 threads.
// 1-pass fp16 MMA: gates = h_hi @ W_hi^T (fp32 acc). W slice in smem.
// 8 warps in 2 k-groups of 4; single-shot h staging; parity-split acc chains.
// ---------------------------------------------------------------------------
#define SM_W     (RPC*1032)                   /* 33024 halves */
#define SM_HROW  520
#define SM_H     (2*32*SM_HROW)               /* 33280 halves */
#define SMEM_PERSIST ((SM_W + SM_H)*2 + (2*32*36 + 32*JPC + RPC)*4)

__global__ __launch_bounds__(256, 1) void lstm_persist(const float* __restrict__ b_ih,
                                                       const float* __restrict__ b_hh) {
    extern __shared__ __align__(16) char smraw[];
    __half* sWhi = (__half*)smraw;               // [32][1032]
    __half* sH   = sWhi + SM_W;                  // [g][32][520]
    float*  gsm  = (float*)(sH + SM_H);          // [2][32][36]
    float*  cst  = gsm + 2*32*36;                // [32][8]
    float*  bias = cst + 32*JPC;                 // [32]

    const int tid  = threadIdx.x;
    const int warp = tid >> 5;
    const int grp  = warp >> 2;                  // k-group 0/1
    const int w2   = warp & 3;
    const int wm = w2 >> 1, wn = w2 & 1;
    const int j0 = blockIdx.x * JPC;

    // Cache W_hh slice (hi only) once
    for (int i = tid; i < RPC*128; i += 256) {
        int r = i >> 7, ci = i & 127;
        int gr = (r >> 3)*HID + j0 + (r & 7);
        ((int4*)(sWhi + r*1032))[ci] = ((const int4*)(g_Whh_hi + (size_t)gr*HID))[ci];
    }
    if (tid < RPC) {
        int gr = (tid >> 3)*HID + j0 + (tid & 7);
        bias[tid] = b_ih[gr] + b_hh[gr];
    }
    for (int i = tid; i < BATCH*JPC; i += 256) cst[i] = 0.0f;
    __syncthreads();

    // h loader: 64 rows (2 grp x 32 batch), 4 threads/row, 16 int4 each
    const int lrow = tid >> 2;                   // 0..63
    const int lgrp = lrow >> 5, lb = lrow & 31;
    const int lq = tid & 3;

    #pragma unroll 1
    for (int s = 0; s < SEQ; s++) {
        const int rb = s & 1, wb = rb ^ 1;
        const __half* __restrict__ hc = g_h_hi[rb];
        __half* __restrict__ hn = g_h_hi[wb];

        // xg prefetch for this thread's cell update
        float xv[4];
        {
            const int b = tid >> 3;
            const float* xr = g_xg + (size_t)(b*SEQ + s)*GATES + j0 + (tid & 7);
            #pragma unroll
            for (int g = 0; g < 4; g++) xv[g] = __ldg(xr + g*HID);
        }

        // single-shot staging of both h group slices
        {
            const int4* src = (const int4*)(hc + lb*HID + lgrp*512);
            int4* dst = (int4*)(sH + (lgrp*32 + lb)*SM_HROW);
            #pragma unroll
            for (int i = 0; i < 16; i++) dst[lq + 4*i] = src[lq + 4*i];
        }
        __syncthreads();

        wmma::fragment<wmma::accumulator, 16, 16, 16, float> accA, accB;
        wmma::fill_fragment(accA, 0.0f);
        wmma::fill_fragment(accB, 0.0f);

        const __half* aBase = sH + (grp*32 + wm*16)*SM_HROW;
        const __half* bBase = sWhi + (wn*16)*1032 + grp*512;
        #pragma unroll
        for (int ki = 0; ki < 32; ki += 2) {
            wmma::fragment<wmma::matrix_a, 16, 16, 16, __half, wmma::row_major> a0, a1;
            wmma::fragment<wmma::matrix_b, 16, 16, 16, __half, wmma::col_major> b0, b1;
            wmma::load_matrix_sync(a0, aBase + ki*16, SM_HROW);
            wmma::load_matrix_sync(b0, bBase + ki*16, 1032);
            wmma::load_matrix_sync(a1, aBase + (ki + 1)*16, SM_HROW);
            wmma::load_matrix_sync(b1, bBase + (ki + 1)*16, 1032);
            wmma::mma_sync(accA, a0, b0, accA);     // two independent chains
            wmma::mma_sync(accB, a1, b1, accB);
        }
        #pragma unroll
        for (int i = 0; i < accA.num_elements; i++) accA.x[i] += accB.x[i];

        wmma::store_matrix_sync(gsm + grp*32*36 + (wm*16)*36 + wn*16, accA, 36,
                                wmma::mem_row_major);
        __syncthreads();

        // fused cell update: one output per thread (32 batch x 8 j)
        {
            const int b  = tid >> 3;
            const int jj = tid & 7;
            const int j  = j0 + jj;
            float iv = gsm[b*36 +  0 + jj] + gsm[32*36 + b*36 +  0 + jj] + xv[0] + bias[ 0 + jj];
            float fv = gsm[b*36 +  8 + jj] + gsm[32*36 + b*36 +  8 + jj] + xv[1] + bias[ 8 + jj];
            float gv = gsm[b*36 + 16 + jj] + gsm[32*36 + b*36 + 16 + jj] + xv[2] + bias[16 + jj];
            float ov = gsm[b*36 + 24 + jj] + gsm[32*36 + b*36 + 24 + jj] + xv[3] + bias[24 + jj];

            float ig = 1.0f / (1.0f + expf(-iv));
            float fg = 1.0f / (1.0f + expf(-fv));
            float gg = tanhf(gv);
            float og = 1.0f / (1.0f + expf(-ov));

            float c = fg * cst[b*JPC + jj] + ig * gg;
            cst[b*JPC + jj] = c;
            float h = og * tanhf(c);
            __half hh = __float2half_rn(h);

            hn[b*HID + j] = hh;
            g_hs_hi[(size_t)(b*SEQ + s)*HID + j] = hh;
        }
        grid_barrier(s);
    }
}

// ---------------------------------------------------------------------------
// Kernel 3: logits = hs @ W_fc^T + b_fc  (M=16384, N=5120pad, K=1024)
// 128x128 tile, 256 threads, 2-pass, KC=32, 2-stage cp.async pipeline.
// ---------------------------------------------------------------------------
#define FC_STG 5120
#define FC_SMEM (6*FC_STG*2 + 8*384*4)

__global__ __launch_bounds__(256) void fc_gemm(const float* __restrict__ b_fc,
                                               float* __restrict__ out) {
    extern __shared__ __align__(16) char sm[];
    __half* As_hi = (__half*)sm;                 // [2][5120]
    __half* Bs_hi = As_hi + 2*FC_STG;
    __half* Bs_lo = Bs_hi + 2*FC_STG;
    float*  Cw    = (float*)(Bs_lo + 2*FC_STG);  // [8][384]

    const int n0 = blockIdx.x * 128;
    const int m0 = blockIdx.y * 128;
    const int tid = threadIdx.x;
    const int warp = tid >> 5;
    const int lane = tid & 31;
    const int wm = warp >> 1, wn = warp & 1;

    wmma::fragment<wmma::accumulator, 16, 16, 16, float> acc[2][4];
    #pragma unroll
    for (int i = 0; i < 2; i++)
        #pragma unroll
        for (int j = 0; j < 4; j++)
            wmma::fill_fragment(acc[i][j], 0.0f);

    auto issue = [&](int st, int k0) {
        const int so = st*FC_STG;
        #pragma unroll
        for (int it = 0; it < 2; it++) {
            const int idx = tid + it*256;
            const int row = idx >> 2, c8 = (idx & 3) * 8;
            __pipeline_memcpy_async(As_hi + so + row*40 + c8,
                                    g_hs_hi + (size_t)(m0 + row)*HID + k0 + c8, 16);
            const int n = n0 + row;
            __pipeline_memcpy_async(Bs_hi + so + row*40 + c8,
                                    g_Wfc_hi + (size_t)n*HID + k0 + c8, 16);
            __pipeline_memcpy_async(Bs_lo + so + row*40 + c8,
                                    g_Wfc_lo + (size_t)n*HID + k0 + c8, 16);
        }
        __pipeline_commit();
    };

    auto compute = [&](int st) {
        const int so = st*FC_STG;
        #pragma unroll
        for (int ks = 0; ks < 2; ks++) {
            wmma::fragment<wmma::matrix_a, 16, 16, 16, __half, wmma::row_major> a_hi[2];
            wmma::fragment<wmma::matrix_b, 16, 16, 16, __half, wmma::col_major> b_hi[4], b_lo[4];
            #pragma unroll
            for (int i = 0; i < 2; i++)
                wmma::load_matrix_sync(a_hi[i], As_hi + so + (wm*32 + i*16)*40 + ks*16, 40);
            #pragma unroll
            for (int j = 0; j < 4; j++) {
                wmma::load_matrix_sync(b_hi[j], Bs_hi + so + (wn*64 + j*16)*40 + ks*16, 40);
                wmma::load_matrix_sync(b_lo[j], Bs_lo + so + (wn*64 + j*16)*40 + ks*16, 40);
            }
            #pragma unroll
            for (int i = 0; i < 2; i++)
                #pragma unroll
                for (int j = 0; j < 4; j++) {
                    wmma::mma_sync(acc[i][j], a_hi[i], b_hi[j], acc[i][j]);
                    wmma::mma_sync(acc[i][j], a_hi[i], b_lo[j], acc[i][j]);
                }
        }
    };

    issue(0, 0);
    #pragma unroll 1
    for (int kc = 0; kc < HID/32 - 1; kc++) {
        issue((kc + 1) & 1, (kc + 1)*32);
        __pipeline_wait_prior(1);
        __syncthreads();
        compute(kc & 1);
        __syncthreads();
    }
    __pipeline_wait_prior(0);
    __syncthreads();
    compute((HID/32 - 1) & 1);

    // epilogue: per-warp staging, add bias, guard VOCAB
    #pragma unroll
    for (int i = 0; i < 2; i++)
        #pragma unroll
        for (int j = 0; j < 4; j++) {
            __syncwarp();
            wmma::store_matrix_sync(Cw + warp*384, acc[i][j], 24, wmma::mem_row_major);
            __syncwarp();
            const int mbase = m0 + wm*32 + i*16;
            const int nbase = n0 + wn*64 + j*16;
            #pragma unroll
            for (int e = 0; e < 8; e++) {
                const int idx = lane*8 + e;
                const int rr = idx >> 4, cc = idx & 15;
                const int v = nbase + cc;
                if (v < VOCAB)
                    out[(size_t)(mbase + rr)*VOCAB + v] = Cw[warp*384 + rr*24 + cc] + b_fc[v];
            }
        }
}

// ---------------------------------------------------------------------------
// Launch
// ---------------------------------------------------------------------------
extern "C" void kernel_launch(void* const* d_in, const int* in_sizes, int n_in,
                              void* d_out, int out_size) {
    const int*   x    = (const int*)  d_in[0];
    const float* emb  = (const float*)d_in[1];
    const float* W_ih = (const float*)d_in[2];
    const float* W_hh = (const float*)d_in[3];
    const float* b_ih = (const float*)d_in[4];
    const float* b_hh = (const float*)d_in[5];
    const float* W_fc = (const float*)d_in[6];
    const float* b_fc = (const float*)d_in[7];
    float* out = (float*)d_out;

    (void)in_sizes; (void)n_in; (void)out_size;

    prep_emb<<<512, 256>>>(emb);
    prep_wih<<<512, 256>>>(W_ih);
    prep_whh<<<512, 256>>>(W_hh);
    prep_wfc<<<512, 256>>>(W_fc);
    init_state<<<(BATCH*HID + 511)/512, 512>>>();

    cudaFuncSetAttribute(embed_gemm, cudaFuncAttributeMaxDynamicSharedMemorySize, EG_SMEM);
    embed_gemm<<<dim3(GATES/128, MROWS/128), 256, EG_SMEM>>>(x);

    cudaFuncSetAttribute(lstm_persist, cudaFuncAttributeMaxDynamicSharedMemorySize,
                         SMEM_PERSIST);
    lstm_persist<<<NCTA, 256, SMEM_PERSIST>>>(b_ih, b_hh);

    cudaFuncSetAttribute(fc_gemm, cudaFuncAttributeMaxDynamicSharedMemorySize, FC_SMEM);
    fc_gemm<<<dim3(VPAD/128, MROWS/128), 256, FC_SMEM>>>(b_fc, out);
}

// round 10
// speedup vs baseline: 1.6772x; 1.1395x over previous
#include <cuda_runtime.h>
#include <cuda_fp16.h>
#include <cuda_pipeline.h>
#include <mma.h>
#include <math.h>

using namespace nvcuda;

#define VOCAB 5000
#define EMB   512
#define HID   1024
#define GATES 4096
#define BATCH 32
#define SEQ   512
#define MROWS (BATCH*SEQ)   /* 16384 */
#define VPAD  5120          /* 40 * 128 */

#define JPC   8             /* j-columns per CTA in recurrence */
#define NCTA  (HID/JPC)     /* 128 persistent CTAs */
#define RPC   (4*JPC)       /* W_hh rows per CTA = 32 */

// ---------------------------------------------------------------------------
// Static device scratch
// ---------------------------------------------------------------------------
__device__ __half g_emb_hi[VOCAB*EMB];
__device__ __half g_Wih_hi[GATES*EMB];
__device__ __half g_Wih_lo[GATES*EMB];
__device__ __half g_Whh_hi[GATES*HID];
__device__ __half g_Wfc_hi[(size_t)VPAD*HID];
__device__ float  g_xg[(size_t)MROWS*GATES];
__device__ __half g_hs_hi[MROWS*HID];
__device__ __half g_h_hi[2][BATCH*HID];      // double-buffered h (fp16 hi only)

// hierarchical barrier state (reset each call; monotonic within a call)
__device__ unsigned g_cnt[8*64];             // 8 counters, 256B apart
__device__ unsigned g_master;
__device__ volatile unsigned g_gen;

// ---------------------------------------------------------------------------
// Prep (2 kernels so lstm_persist is the 4th stream launch -> ncu slot)
// ---------------------------------------------------------------------------
__device__ __forceinline__ void split1(float f, __half* hi, __half* lo, size_t i) {
    __half h = __float2half_rn(f);
    hi[i] = h;
    lo[i] = __float2half_rn(f - __half2float(h));
}

__global__ void prep_weights(const float* __restrict__ wih,
                             const float* __restrict__ whh,
                             const float* __restrict__ wfc) {
    const size_t stride = (size_t)gridDim.x*blockDim.x;
    for (size_t i = blockIdx.x*blockDim.x + threadIdx.x; i < GATES*EMB; i += stride)
        split1(wih[i], g_Wih_hi, g_Wih_lo, i);
    for (size_t i = blockIdx.x*blockDim.x + threadIdx.x; i < GATES*HID; i += stride)
        g_Whh_hi[i] = __float2half_rn(whh[i]);
    for (size_t i = blockIdx.x*blockDim.x + threadIdx.x; i < (size_t)VPAD*HID; i += stride)
        g_Wfc_hi[i] = __float2half_rn(i < (size_t)VOCAB*HID ? wfc[i] : 0.0f);
}

__global__ void prep_emb_init(const float* __restrict__ emb) {
    const size_t stride = (size_t)gridDim.x*blockDim.x;
    const size_t t0 = blockIdx.x*blockDim.x + threadIdx.x;
    for (size_t i = t0; i < VOCAB*EMB; i += stride)
        g_emb_hi[i] = __float2half_rn(emb[i]);
    for (size_t i = t0; i < BATCH*HID; i += stride)
        g_h_hi[0][i] = __float2half_rn(0.0f);
    if (t0 < 8*64) g_cnt[t0] = 0u;
    if (t0 == 0) { g_master = 0u; g_gen = 0u; }
}

// ---------------------------------------------------------------------------
// Kernel 1: xg = emb[x] @ W_ih^T  (M=16384, N=4096, K=512), 2-pass
// (a_hi*b_hi + a_hi*b_lo).  128x128 tile, 256 threads, KC=32, 2-stage cp.async.
// ---------------------------------------------------------------------------
#define EG_STG 5120                       /* halves per array per stage */
#define EG_SMEM (6*EG_STG*2 + 128*4)

__global__ __launch_bounds__(256) void embed_gemm(const int* __restrict__ x) {
    extern __shared__ __align__(16) char sm[];
    __half* As_hi = (__half*)sm;                 // [2][5120]
    __half* Bs_hi = As_hi + 2*EG_STG;
    __half* Bs_lo = Bs_hi + 2*EG_STG;
    int*    rowidx = (int*)(Bs_lo + 2*EG_STG);

    const int n0 = blockIdx.x * 128;
    const int m0 = blockIdx.y * 128;
    const int tid = threadIdx.x;
    const int warp = tid >> 5;
    const int wm = warp >> 1, wn = warp & 1;

    if (tid < 128) rowidx[tid] = x[m0 + tid];
    __syncthreads();

    wmma::fragment<wmma::accumulator, 16, 16, 16, float> acc[2][4];
    #pragma unroll
    for (int i = 0; i < 2; i++)
        #pragma unroll
        for (int j = 0; j < 4; j++)
            wmma::fill_fragment(acc[i][j], 0.0f);

    auto issue = [&](int st, int k0) {
        const int so = st*EG_STG;
        #pragma unroll
        for (int it = 0; it < 2; it++) {
            const int idx = tid + it*256;
            const int row = idx >> 2, c8 = (idx & 3) * 8;
            const int r = rowidx[row];
            __pipeline_memcpy_async(As_hi + so + row*40 + c8, g_emb_hi + (size_t)r*EMB + k0 + c8, 16);
            const int n = n0 + row;
            __pipeline_memcpy_async(Bs_hi + so + row*40 + c8, g_Wih_hi + (size_t)n*EMB + k0 + c8, 16);
            __pipeline_memcpy_async(Bs_lo + so + row*40 + c8, g_Wih_lo + (size_t)n*EMB + k0 + c8, 16);
        }
        __pipeline_commit();
    };

    auto compute = [&](int st) {
        const int so = st*EG_STG;
        #pragma unroll
        for (int ks = 0; ks < 2; ks++) {
            wmma::fragment<wmma::matrix_a, 16, 16, 16, __half, wmma::row_major> a_hi[2];
            wmma::fragment<wmma::matrix_b, 16, 16, 16, __half, wmma::col_major> b_hi[4], b_lo[4];
            #pragma unroll
            for (int i = 0; i < 2; i++)
                wmma::load_matrix_sync(a_hi[i], As_hi + so + (wm*32 + i*16)*40 + ks*16, 40);
            #pragma unroll
            for (int j = 0; j < 4; j++) {
                wmma::load_matrix_sync(b_hi[j], Bs_hi + so + (wn*64 + j*16)*40 + ks*16, 40);
                wmma::load_matrix_sync(b_lo[j], Bs_lo + so + (wn*64 + j*16)*40 + ks*16, 40);
            }
            #pragma unroll
            for (int i = 0; i < 2; i++)
                #pragma unroll
                for (int j = 0; j < 4; j++) {
                    wmma::mma_sync(acc[i][j], a_hi[i], b_hi[j], acc[i][j]);
                    wmma::mma_sync(acc[i][j], a_hi[i], b_lo[j], acc[i][j]);
                }
        }
    };

    issue(0, 0);
    #pragma unroll 1
    for (int kc = 0; kc < EMB/32 - 1; kc++) {
        issue((kc + 1) & 1, (kc + 1)*32);
        __pipeline_wait_prior(1);
        __syncthreads();
        compute(kc & 1);
        __syncthreads();
    }
    __pipeline_wait_prior(0);
    __syncthreads();
    compute((EMB/32 - 1) & 1);

    #pragma unroll
    for (int i = 0; i < 2; i++)
        #pragma unroll
        for (int j = 0; j < 4; j++)
            wmma::store_matrix_sync(
                g_xg + (size_t)(m0 + wm*32 + i*16)*GATES + n0 + wn*64 + j*16,
                acc[i][j], GATES, wmma::mem_row_major);
}

// ---------------------------------------------------------------------------
// Hierarchical grid barrier (tid0-only polling)
// ---------------------------------------------------------------------------
__device__ __forceinline__ void grid_barrier(int s) {
    __syncthreads();
    if (threadIdx.x == 0) {
        __threadfence();
        const unsigned c = blockIdx.x & 7u;
        if (atomicAdd(&g_cnt[c*64], 1u) == 16u*(unsigned)(s + 1) - 1u) {
            if (atomicAdd(&g_master, 1u) == 8u*(unsigned)(s + 1) - 1u) {
                __threadfence();
                g_gen = (unsigned)(s + 1);
            }
        }
        while (g_gen < (unsigned)(s + 1)) __nanosleep(16);
        __threadfence();
    }
    __syncthreads();
}

// ---------------------------------------------------------------------------
// Kernel 2: persistent LSTM recurrence. 128 CTAs x 256 threads.
// 1-pass fp16 MMA: gates = h_hi @ W_hi^T (fp32 acc). W slice in smem.
// 8 warps in 2 k-groups of 4; single-shot h staging; parity-split acc chains.
// ---------------------------------------------------------------------------
#define SM_W     (RPC*1032)                   /* 33024 halves */
#define SM_HROW  520
#define SM_H     (2*32*SM_HROW)               /* 33280 halves */
#define SMEM_PERSIST ((SM_W + SM_H)*2 + (2*32*36 + 32*JPC + RPC)*4)

__global__ __launch_bounds__(256, 1) void lstm_persist(const float* __restrict__ b_ih,
                                                       const float* __restrict__ b_hh) {
    extern __shared__ __align__(16) char smraw[];
    __half* sWhi = (__half*)smraw;               // [32][1032]
    __half* sH   = sWhi + SM_W;                  // [g][32][520]
    float*  gsm  = (float*)(sH + SM_H);          // [2][32][36]
    float*  cst  = gsm + 2*32*36;                // [32][8]
    float*  bias = cst + 32*JPC;                 // [32]

    const int tid  = threadIdx.x;
    const int warp = tid >> 5;
    const int grp  = warp >> 2;                  // k-group 0/1
    const int w2   = warp & 3;
    const int wm = w2 >> 1, wn = w2 & 1;
    const int j0 = blockIdx.x * JPC;

    // Cache W_hh slice (hi only) once
    for (int i = tid; i < RPC*128; i += 256) {
        int r = i >> 7, ci = i & 127;
        int gr = (r >> 3)*HID + j0 + (r & 7);
        ((int4*)(sWhi + r*1032))[ci] = ((const int4*)(g_Whh_hi + (size_t)gr*HID))[ci];
    }
    if (tid < RPC) {
        int gr = (tid >> 3)*HID + j0 + (tid & 7);
        bias[tid] = b_ih[gr] + b_hh[gr];
    }
    for (int i = tid; i < BATCH*JPC; i += 256) cst[i] = 0.0f;
    __syncthreads();

    // h loader: 64 rows (2 grp x 32 batch), 4 threads/row, 16 int4 each
    const int lrow = tid >> 2;                   // 0..63
    const int lgrp = lrow >> 5, lb = lrow & 31;
    const int lq = tid & 3;

    #pragma unroll 1
    for (int s = 0; s < SEQ; s++) {
        const int rb = s & 1, wb = rb ^ 1;
        const __half* __restrict__ hc = g_h_hi[rb];
        __half* __restrict__ hn = g_h_hi[wb];

        // xg prefetch for this thread's cell update
        float xv[4];
        {
            const int b = tid >> 3;
            const float* xr = g_xg + (size_t)(b*SEQ + s)*GATES + j0 + (tid & 7);
            #pragma unroll
            for (int g = 0; g < 4; g++) xv[g] = __ldg(xr + g*HID);
        }

        // single-shot staging of both h group slices
        {
            const int4* src = (const int4*)(hc + lb*HID + lgrp*512);
            int4* dst = (int4*)(sH + (lgrp*32 + lb)*SM_HROW);
            #pragma unroll
            for (int i = 0; i < 16; i++) dst[lq + 4*i] = src[lq + 4*i];
        }
        __syncthreads();

        wmma::fragment<wmma::accumulator, 16, 16, 16, float> accA, accB;
        wmma::fill_fragment(accA, 0.0f);
        wmma::fill_fragment(accB, 0.0f);

        const __half* aBase = sH + (grp*32 + wm*16)*SM_HROW;
        const __half* bBase = sWhi + (wn*16)*1032 + grp*512;
        #pragma unroll
        for (int ki = 0; ki < 32; ki += 2) {
            wmma::fragment<wmma::matrix_a, 16, 16, 16, __half, wmma::row_major> a0, a1;
            wmma::fragment<wmma::matrix_b, 16, 16, 16, __half, wmma::col_major> b0, b1;
            wmma::load_matrix_sync(a0, aBase + ki*16, SM_HROW);
            wmma::load_matrix_sync(b0, bBase + ki*16, 1032);
            wmma::load_matrix_sync(a1, aBase + (ki + 1)*16, SM_HROW);
            wmma::load_matrix_sync(b1, bBase + (ki + 1)*16, 1032);
            wmma::mma_sync(accA, a0, b0, accA);     // two independent chains
            wmma::mma_sync(accB, a1, b1, accB);
        }
        #pragma unroll
        for (int i = 0; i < accA.num_elements; i++) accA.x[i] += accB.x[i];

        wmma::store_matrix_sync(gsm + grp*32*36 + (wm*16)*36 + wn*16, accA, 36,
                                wmma::mem_row_major);
        __syncthreads();

        // fused cell update: one output per thread (32 batch x 8 j)
        {
            const int b  = tid >> 3;
            const int jj = tid & 7;
            const int j  = j0 + jj;
            float iv = gsm[b*36 +  0 + jj] + gsm[32*36 + b*36 +  0 + jj] + xv[0] + bias[ 0 + jj];
            float fv = gsm[b*36 +  8 + jj] + gsm[32*36 + b*36 +  8 + jj] + xv[1] + bias[ 8 + jj];
            float gv = gsm[b*36 + 16 + jj] + gsm[32*36 + b*36 + 16 + jj] + xv[2] + bias[16 + jj];
            float ov = gsm[b*36 + 24 + jj] + gsm[32*36 + b*36 + 24 + jj] + xv[3] + bias[24 + jj];

            float ig = 1.0f / (1.0f + expf(-iv));
            float fg = 1.0f / (1.0f + expf(-fv));
            float gg = tanhf(gv);
            float og = 1.0f / (1.0f + expf(-ov));

            float c = fg * cst[b*JPC + jj] + ig * gg;
            cst[b*JPC + jj] = c;
            float h = og * tanhf(c);
            __half hh = __float2half_rn(h);

            hn[b*HID + j] = hh;
            g_hs_hi[(size_t)(b*SEQ + s)*HID + j] = hh;
        }
        grid_barrier(s);
    }
}

// ---------------------------------------------------------------------------
// Kernel 3: logits = hs @ W_fc^T + b_fc  (M=16384, N=5120pad, K=1024)
// 128x128 tile, 256 threads, 1-pass fp16, KC=32, 2-stage cp.async pipeline.
// ---------------------------------------------------------------------------
#define FC_STG 5120
#define FC_SMEM (4*FC_STG*2 + 8*384*4)

__global__ __launch_bounds__(256) void fc_gemm(const float* __restrict__ b_fc,
                                               float* __restrict__ out) {
    extern __shared__ __align__(16) char sm[];
    __half* As_hi = (__half*)sm;                 // [2][5120]
    __half* Bs_hi = As_hi + 2*FC_STG;
    float*  Cw    = (float*)(Bs_hi + 2*FC_STG);  // [8][384]

    const int n0 = blockIdx.x * 128;
    const int m0 = blockIdx.y * 128;
    const int tid = threadIdx.x;
    const int warp = tid >> 5;
    const int lane = tid & 31;
    const int wm = warp >> 1, wn = warp & 1;

    wmma::fragment<wmma::accumulator, 16, 16, 16, float> acc[2][4];
    #pragma unroll
    for (int i = 0; i < 2; i++)
        #pragma unroll
        for (int j = 0; j < 4; j++)
            wmma::fill_fragment(acc[i][j], 0.0f);

    auto issue = [&](int st, int k0) {
        const int so = st*FC_STG;
        #pragma unroll
        for (int it = 0; it < 2; it++) {
            const int idx = tid + it*256;
            const int row = idx >> 2, c8 = (idx & 3) * 8;
            __pipeline_memcpy_async(As_hi + so + row*40 + c8,
                                    g_hs_hi + (size_t)(m0 + row)*HID + k0 + c8, 16);
            const int n = n0 + row;
            __pipeline_memcpy_async(Bs_hi + so + row*40 + c8,
                                    g_Wfc_hi + (size_t)n*HID + k0 + c8, 16);
        }
        __pipeline_commit();
    };

    auto compute = [&](int st) {
        const int so = st*FC_STG;
        #pragma unroll
        for (int ks = 0; ks < 2; ks++) {
            wmma::fragment<wmma::matrix_a, 16, 16, 16, __half, wmma::row_major> a_hi[2];
            wmma::fragment<wmma::matrix_b, 16, 16, 16, __half, wmma::col_major> b_hi[4];
            #pragma unroll
            for (int i = 0; i < 2; i++)
                wmma::load_matrix_sync(a_hi[i], As_hi + so + (wm*32 + i*16)*40 + ks*16, 40);
            #pragma unroll
            for (int j = 0; j < 4; j++)
                wmma::load_matrix_sync(b_hi[j], Bs_hi + so + (wn*64 + j*16)*40 + ks*16, 40);
            #pragma unroll
            for (int i = 0; i < 2; i++)
                #pragma unroll
                for (int j = 0; j < 4; j++)
                    wmma::mma_sync(acc[i][j], a_hi[i], b_hi[j], acc[i][j]);
        }
    };

    issue(0, 0);
    #pragma unroll 1
    for (int kc = 0; kc < HID/32 - 1; kc++) {
        issue((kc + 1) & 1, (kc + 1)*32);
        __pipeline_wait_prior(1);
        __syncthreads();
        compute(kc & 1);
        __syncthreads();
    }
    __pipeline_wait_prior(0);
    __syncthreads();
    compute((HID/32 - 1) & 1);

    // epilogue: per-warp staging, add bias, guard VOCAB
    #pragma unroll
    for (int i = 0; i < 2; i++)
        #pragma unroll
        for (int j = 0; j < 4; j++) {
            __syncwarp();
            wmma::store_matrix_sync(Cw + warp*384, acc[i][j], 24, wmma::mem_row_major);
            __syncwarp();
            const int mbase = m0 + wm*32 + i*16;
            const int nbase = n0 + wn*64 + j*16;
            #pragma unroll
            for (int e = 0; e < 8; e++) {
                const int idx = lane*8 + e;
                const int rr = idx >> 4, cc = idx & 15;
                const int v = nbase + cc;
                if (v < VOCAB)
                    out[(size_t)(mbase + rr)*VOCAB + v] = Cw[warp*384 + rr*24 + cc] + b_fc[v];
            }
        }
}

// ---------------------------------------------------------------------------
// Launch (order matters: lstm_persist must be the 4th launch for ncu)
// ---------------------------------------------------------------------------
extern "C" void kernel_launch(void* const* d_in, const int* in_sizes, int n_in,
                              void* d_out, int out_size) {
    const int*   x    = (const int*)  d_in[0];
    const float* emb  = (const float*)d_in[1];
    const float* W_ih = (const float*)d_in[2];
    const float* W_hh = (const float*)d_in[3];
    const float* b_ih = (const float*)d_in[4];
    const float* b_hh = (const float*)d_in[5];
    const float* W_fc = (const float*)d_in[6];
    const float* b_fc = (const float*)d_in[7];
    float* out = (float*)d_out;

    (void)in_sizes; (void)n_in; (void)out_size;

    prep_weights<<<1024, 256>>>(W_ih, W_hh, W_fc);      // launch 1
    prep_emb_init<<<1024, 256>>>(emb);                  // launch 2

    cudaFuncSetAttribute(embed_gemm, cudaFuncAttributeMaxDynamicSharedMemorySize, EG_SMEM);
    embed_gemm<<<dim3(GATES/128, MROWS/128), 256, EG_SMEM>>>(x);   // launch 3

    cudaFuncSetAttribute(lstm_persist, cudaFuncAttributeMaxDynamicSharedMemorySize,
                         SMEM_PERSIST);
    lstm_persist<<<NCTA, 256, SMEM_PERSIST>>>(b_ih, b_hh);         // launch 4 (ncu slot)

    cudaFuncSetAttribute(fc_gemm, cudaFuncAttributeMaxDynamicSharedMemorySize, FC_SMEM);
    fc_gemm<<<dim3(VPAD/128, MROWS/128), 256, FC_SMEM>>>(b_fc, out);
}